// round 1
// baseline (speedup 1.0000x reference)
#include <cuda_runtime.h>
#include <math.h>

#define DS   128
#define DSM  (DS - 1)
#define D3   (DS * DS * DS)

#define TXD  32
#define TYD  4
#define TZD  4
#define NTHR (TXD * TYD * TZD)

#define HX   (TXD + 4)      // 36
#define HY   (TYD + 4)      // 8
#define HZ   (TZD + 4)      // 8
#define HXY  (HX * HY)
#define HTOT (HX * HY * HZ) // 2304

__device__ __forceinline__ float fast_sqrt(float x) {
    float r; asm("sqrt.approx.f32 %0, %1;" : "=f"(r) : "f"(x)); return r;
}
__device__ __forceinline__ float fast_rcp(float x) {
    float r; asm("rcp.approx.f32 %0, %1;" : "=f"(r) : "f"(x)); return r;
}

// One stencil contribution (offset o into shared halo arrays).
#define CONTRIB(o)                                                            \
    {                                                                         \
        float dx = X - SX[(o)], dy = Y - SY[(o)], dz = Z - SZ[(o)];           \
        float sq = dx * dx + dy * dy + dz * dz;                               \
        float dist = fast_sqrt(sq + 1e-20f);                                  \
        if (dist < 2.0f) {                                                    \
            float rcd = fast_rcp(fmaxf(dist, 1e-4f));                         \
            float vn = ((VX - SVX[(o)]) * dx + (VY - SVY[(o)]) * dy +         \
                        (VZ - SVZ[(o)]) * dz) * rcd;                          \
            float coef = (KN * (dist - 2.0f) + ETA * vn) * rcd;               \
            fx += coef * dx; fy += coef * dy; fz += coef * dz;                \
        }                                                                     \
    }

__global__ __launch_bounds__(NTHR, 1) void dem_step(
    const float* __restrict__ xg,  const float* __restrict__ yg,
    const float* __restrict__ zg,  const float* __restrict__ vxg,
    const float* __restrict__ vyg, const float* __restrict__ vzg,
    const float* __restrict__ mg,  float* __restrict__ out, float ETA)
{
    extern __shared__ float sm[];
    float* SX  = sm;
    float* SY  = sm + HTOT;
    float* SZ  = sm + 2 * HTOT;
    float* SVX = sm + 3 * HTOT;
    float* SVY = sm + 4 * HTOT;
    float* SVZ = sm + 5 * HTOT;

    const int x0 = blockIdx.x * TXD;
    const int y0 = blockIdx.y * TYD;
    const int z0 = blockIdx.z * TZD;
    const int tid = threadIdx.x + TXD * (threadIdx.y + TYD * threadIdx.z);

    // Cooperative halo fill (periodic wrap: & 127)
    for (int i = tid; i < HTOT; i += NTHR) {
        int lx = i % HX;
        int t  = i / HX;
        int ly = t % HY;
        int lz = t / HY;
        int gx = (x0 + lx - 2) & DSM;
        int gy = (y0 + ly - 2) & DSM;
        int gz = (z0 + lz - 2) & DSM;
        int g  = (gz << 14) | (gy << 7) | gx;
        SX[i]  = __ldg(xg + g);
        SY[i]  = __ldg(yg + g);
        SZ[i]  = __ldg(zg + g);
        SVX[i] = __ldg(vxg + g);
        SVY[i] = __ldg(vyg + g);
        SVZ[i] = __ldg(vzg + g);
    }
    __syncthreads();

    const int gx = x0 + threadIdx.x;
    const int gy = y0 + threadIdx.y;
    const int gz = z0 + threadIdx.z;
    const float m = __ldg(mg + ((gz << 14) | (gy << 7) | gx));

    // Whole warp empty (boundary slabs etc.) -> done
    if (__ballot_sync(0xFFFFFFFFu, m != 0.0f) == 0u) return;
    if (m == 0.0f) return;  // empty cell: output stays zero (pre-memset)

    const int c = (threadIdx.z + 2) * HXY + (threadIdx.y + 2) * HX + (threadIdx.x + 2);
    const float X  = SX[c],  Y  = SY[c],  Z  = SZ[c];
    const float VX = SVX[c], VY = SVY[c], VZ = SVZ[c];

    const float KN = 500000.0f;
    float fx = 0.0f, fy = 0.0f, fz = 0.0f;

    // 80 shifts with s^2 in [1,7]: the only shifts where two occupied
    // particles (pos = idx +- 0.2) can have dist < 2. Fully unrolled:
    // offsets become LDS immediates.
    #pragma unroll
    for (int oz = -2; oz <= 2; ++oz)
    #pragma unroll
    for (int oy = -2; oy <= 2; ++oy)
    #pragma unroll
    for (int ox = -2; ox <= 2; ++ox) {
        const int s2 = oz * oz + oy * oy + ox * ox;
        if (s2 == 0 || s2 > 7) continue;
        const int o = c + oz * HXY + oy * HX + ox;
        CONTRIB(o);
    }

    // Excluded shifts (s^2 >= 8) can only contribute via the "empty neighbor"
    // fake contact, which requires |own position| < 2 (origin-corner cells).
    // Extremely rare -> compact runtime loop.
    if (X * X + Y * Y + Z * Z < 4.0f) {
        #pragma unroll 1
        for (int oz = -2; oz <= 2; ++oz)
        #pragma unroll 1
        for (int oy = -2; oy <= 2; ++oy)
        #pragma unroll 1
        for (int ox = -2; ox <= 2; ++ox) {
            int s2 = oz * oz + oy * oy + ox * ox;
            if (s2 <= 7) continue;
            int o = c + oz * HXY + oy * HX + ox;
            CONTRIB(o);
        }
    }

    // Boundary overlap forces (mask == 1 here)
    float bl = (X != 0.0f && X < 1.0f) ? 1.0f : 0.0f;
    float br = (X > 126.0f) ? 1.0f : 0.0f;
    float bb = (Y != 0.0f && Y < 1.0f) ? 1.0f : 0.0f;
    float bt = (Y > 126.0f) ? 1.0f : 0.0f;
    float bf = (Z != 0.0f && Z < 1.0f) ? 1.0f : 0.0f;
    float bk = (Z > 126.0f) ? 1.0f : 0.0f;
    float fxb = KN * bl * (1.0f - X) - KN * br * (X - 126.0f) - ETA * VX * (bl + br);
    float fyb = KN * bb * (1.0f - Y) - KN * bt * (Y - 126.0f) - ETA * VY * (bb + bt);
    float fzb = KN * bf * (1.0f - Z) - KN * bk * (Z - 126.0f) - ETA * VZ * (bf + bk);

    float vxn = VX + 1e-4f * (-fx + fxb);
    float vyn = VY + 1e-4f * (-9.8f - fy + fyb);
    float vzn = VZ + 1e-4f * (-fz + fzb);
    float xn = X + 1e-4f * vxn;
    float yn = Y + 1e-4f * vyn;
    float zn = Z + 1e-4f * vzn;

    // Cell-list relocation: round-half-even like jnp.round; component == 0
    // invalid (reference), out-of-range dropped (JAX scatter drop mode).
    int cx = __float2int_rn(xn);
    int cy = __float2int_rn(yn);
    int cz = __float2int_rn(zn);
    if (cx >= 1 && cx <= 127 && cy >= 1 && cy <= 127 && cz >= 1 && cz <= 127) {
        int l = (cz << 14) | (cy << 7) | cx;
        out[l]          = xn;
        out[D3 + l]     = yn;
        out[2 * D3 + l] = zn;
        out[3 * D3 + l] = vxn;
        out[4 * D3 + l] = vyn;
        out[5 * D3 + l] = vzn;
        out[6 * D3 + l] = 1.0f;
    }
}

extern "C" void kernel_launch(void* const* d_in, const int* in_sizes, int n_in,
                              void* d_out, int out_size)
{
    const float* xg  = (const float*)d_in[0];
    const float* yg  = (const float*)d_in[1];
    const float* zg  = (const float*)d_in[2];
    const float* vxg = (const float*)d_in[3];
    const float* vyg = (const float*)d_in[4];
    const float* vzg = (const float*)d_in[5];
    const float* mg  = (const float*)d_in[6];
    float* out = (float*)d_out;

    // Reference's "zero at lo" pass: every occupied cell is its own lo and all
    // other cells are already zero -> full zero-init then scatter at ln.
    cudaMemsetAsync(d_out, 0, (size_t)out_size * sizeof(float), 0);

    // ETA exactly as reference computes it (double precision, then fp32 use)
    double alpha = -log(0.7) / M_PI;
    double gamma = alpha / sqrt(alpha * alpha + 1.0);
    float  eta   = (float)(2.0 * gamma * sqrt(500000.0 * 1.0));

    const size_t smem = 6 * HTOT * sizeof(float);  // 55296 B
    cudaFuncSetAttribute(dem_step, cudaFuncAttributeMaxDynamicSharedMemorySize, (int)smem);

    dim3 block(TXD, TYD, TZD);
    dim3 grid(DS / TXD, DS / TYD, DS / TZD);
    dem_step<<<grid, block, smem>>>(xg, yg, zg, vxg, vyg, vzg, mg, out, eta);
}